// round 6
// baseline (speedup 1.0000x reference)
#include <cuda_runtime.h>
#include <cstdint>
#include <cstring>

#define S_   32
#define IN_  2048
#define OUT_ 2048
#define TPB  256
#define SGRP 8                    // samples per register group
#define NPAIR (SGRP / 2)
#define NGRP (S_ / SGRP)

// ---------------------------------------------------------------------------
// Host-side threefry2x32 (subkey derivation for jax.random.key(42) only)
// ---------------------------------------------------------------------------
static inline uint32_t h_rotl32(uint32_t x, int r) {
    return (x << r) | (x >> (32 - r));
}
static inline void h_round(uint32_t& x0, uint32_t& x1, int r) {
    x0 += x1; x1 = h_rotl32(x1, r); x1 ^= x0;
}
static void h_threefry2x32(uint32_t k0, uint32_t k1, uint32_t c0, uint32_t c1,
                           uint32_t& o0, uint32_t& o1)
{
    const uint32_t k2 = k0 ^ k1 ^ 0x1BD11BDAu;
    uint32_t x0 = c0 + k0, x1 = c1 + k1;
    h_round(x0,x1,13); h_round(x0,x1,15); h_round(x0,x1,26); h_round(x0,x1,6);
    x0 += k1; x1 += k2 + 1u;
    h_round(x0,x1,17); h_round(x0,x1,29); h_round(x0,x1,16); h_round(x0,x1,24);
    x0 += k2; x1 += k0 + 2u;
    h_round(x0,x1,13); h_round(x0,x1,15); h_round(x0,x1,26); h_round(x0,x1,6);
    x0 += k0; x1 += k1 + 3u;
    h_round(x0,x1,17); h_round(x0,x1,29); h_round(x0,x1,16); h_round(x0,x1,24);
    x0 += k1; x1 += k2 + 4u;
    h_round(x0,x1,13); h_round(x0,x1,15); h_round(x0,x1,26); h_round(x0,x1,6);
    x0 += k2; x1 += k0 + 5u;
    o0 = x0; o1 = x1;
}

// ---------------------------------------------------------------------------
// Param structs (opaque to ptxas -> no strength reduction / remat).
// ---------------------------------------------------------------------------
struct TFKeys {
    uint32_t k0, k1, k2;
    uint32_t j1, j2, j3, j4, j5;   // k2+1, k0+2, k1+3, k2+4, k0+5
};
struct RotM {                      // 2^R for each rotation amount
    uint32_t m13, m15, m26, m6, m17, m29, m16, m24;
};
struct PC {                        // broadcast-packed f32x2 constants
    uint64_t c0, c1, c2, c3, c4, c5, c6, c7, c8;   // Giles central, sqrt2-folded
    uint64_t one2, negone2, negln2_2, m2p5_2;
};

// ---------------------------------------------------------------------------
// f32x2 helpers
// ---------------------------------------------------------------------------
__device__ __forceinline__ uint64_t pk2(float a, float b) {
    uint64_t r; asm("mov.b64 %0, {%1, %2};" : "=l"(r) : "f"(a), "f"(b)); return r;
}
__device__ __forceinline__ void upk2(float& a, float& b, uint64_t v) {
    asm("mov.b64 {%0, %1}, %2;" : "=f"(a), "=f"(b) : "l"(v));
}
__device__ __forceinline__ uint64_t fma2(uint64_t a, uint64_t b, uint64_t c) {
    uint64_t r; asm("fma.rn.f32x2 %0, %1, %2, %3;" : "=l"(r) : "l"(a), "l"(b), "l"(c)); return r;
}
__device__ __forceinline__ uint64_t mul2(uint64_t a, uint64_t b) {
    uint64_t r; asm("mul.rn.f32x2 %0, %1, %2;" : "=l"(r) : "l"(a), "l"(b)); return r;
}

// ---------------------------------------------------------------------------
// Device threefry round:
//   x0 += x1                 IMAD (fma pipe, opaque one)
//   rot = x1 * m (wide)      IMAD.WIDE.U32 (fma pipe, opaque m — forced asm)
//   x1 = (lo|hi) ^ x0        single LOP3 (alu pipe)
// ---------------------------------------------------------------------------
__device__ __forceinline__ uint32_t addi(uint32_t a, uint32_t b, uint32_t one) {
    return a * one + b;            // IMAD
}
__device__ __forceinline__ uint64_t mulwide(uint32_t a, uint32_t b) {
    uint64_t r; asm("mul.wide.u32 %0, %1, %2;" : "=l"(r) : "r"(a), "r"(b)); return r;
}
__device__ __forceinline__ void tfrm(uint32_t& x0, uint32_t& x1, uint32_t m, uint32_t one) {
    x0 = addi(x0, x1, one);
    const uint64_t p = mulwide(x1, m);
    x1 = (((uint32_t)p) | ((uint32_t)(p >> 32))) ^ x0;
}

__device__ __forceinline__ uint32_t threefry_from_x1(const TFKeys k, uint32_t x1,
                                                     uint32_t one, const RotM rm) {
    uint32_t x0 = k.k0;            // c0 == 0

    tfrm(x0,x1,rm.m13,one); tfrm(x0,x1,rm.m15,one); tfrm(x0,x1,rm.m26,one); tfrm(x0,x1,rm.m6,one);
    x0 = addi(x0, k.k1, one); x1 = addi(x1, k.j1, one);
    tfrm(x0,x1,rm.m17,one); tfrm(x0,x1,rm.m29,one); tfrm(x0,x1,rm.m16,one); tfrm(x0,x1,rm.m24,one);
    x0 = addi(x0, k.k2, one); x1 = addi(x1, k.j2, one);
    tfrm(x0,x1,rm.m13,one); tfrm(x0,x1,rm.m15,one); tfrm(x0,x1,rm.m26,one); tfrm(x0,x1,rm.m6,one);
    x0 = addi(x0, k.k0, one); x1 = addi(x1, k.j3, one);
    tfrm(x0,x1,rm.m17,one); tfrm(x0,x1,rm.m29,one); tfrm(x0,x1,rm.m16,one); tfrm(x0,x1,rm.m24,one);
    x0 = addi(x0, k.k1, one); x1 = addi(x1, k.j4, one);
    tfrm(x0,x1,rm.m13,one); tfrm(x0,x1,rm.m15,one); tfrm(x0,x1,rm.m26,one); tfrm(x0,x1,rm.m6,one);
    x0 = addi(x0, k.k2, one); x1 = addi(x1, k.j5, one);

    return x0 ^ x1;
}

// u from bits (bit-exact vs JAX path): v=(float)(bits>>9) exact 23-bit,
// u = RN(v*2^-22 - 0.99999994)
__device__ __forceinline__ float u_of(uint32_t bits) {
    float v = (float)(bits >> 9);
    return __fmaf_rn(v, 0x1p-22f, -0.99999994f);
}

// scalar tail eps (sqrt2-folded coeffs); l = log2(1-u^2) already computed
__device__ __forceinline__ float tail_eps(float u, float l) {
    float w  = __fmul_rn(l, -0.69314718f);
    float ws = __fsqrt_rn(w) - 3.0f;
    float p;
    p = -2.8314684e-04f;
    p = __fmaf_rn(p, ws, 1.4276590e-04f);
    p = __fmaf_rn(p, ws, 1.9082523e-03f);
    p = __fmaf_rn(p, ws, -5.1950109e-03f);
    p = __fmaf_rn(p, ws, 8.1168911e-03f);
    p = __fmaf_rn(p, ws, -1.0779785e-02f);
    p = __fmaf_rn(p, ws, 1.3348580e-02f);
    p = __fmaf_rn(p, ws, 1.4165810e+00f);
    p = __fmaf_rn(p, ws, 4.0064341e+00f);
    return __fmul_rn(p, u);
}

// scalar full eps for the (cold) bias path
__device__ __forceinline__ float bits_to_eps_scalar(uint32_t bits) {
    float u = u_of(bits);
    float t = __fmul_rn(u, u);
    float y = __fadd_rn(1.0f, -t);
    float l = __log2f(y);
    float wc = __fmaf_rn(l, -0.69314718f, -2.5f);
    float p;
    p = 3.9740742e-08f;
    p = __fmaf_rn(p, wc, 4.8546264e-07f);
    p = __fmaf_rn(p, wc, -4.9828285e-06f);
    p = __fmaf_rn(p, wc, -6.2105203e-06f);
    p = __fmaf_rn(p, wc, 3.0911997e-04f);
    p = __fmaf_rn(p, wc, -1.7730364e-03f);
    p = __fmaf_rn(p, wc, -5.9081367e-03f);
    p = __fmaf_rn(p, wc, 3.4880266e-01f);
    p = __fmaf_rn(p, wc, 2.1233135e+00f);
    if (wc >= 2.5f) p = tail_eps(u, l) , p = p; // unreachable shape-keeper
    if (wc >= 2.5f) return tail_eps(u, l);
    return __fmul_rn(p, u);
}

#define UTH 0.9966446f   // |u| >= UTH  <=>  w >= 5 (tail)

// ---------------------------------------------------------------------------
// One block per output column o. 4 groups of 8 samples; samples processed in
// f32x2 pairs. No smem in the mainloop; shuffle reduction at group end.
// ---------------------------------------------------------------------------
__global__ void __launch_bounds__(TPB)
bayes_linear_kernel(const float* __restrict__ x,
                    const float* __restrict__ wmu,
                    const float* __restrict__ wsig,
                    const float* __restrict__ bmu,
                    const float* __restrict__ bsig,
                    float* __restrict__ out,
                    TFKeys wk, TFKeys bk, RotM rm, PC pc,
                    uint32_t one, uint32_t c22 /* == 1<<22, opaque */)
{
    __shared__ float red[S_][9];   // [sample][warp] partials (pad to 9)

    const int o    = blockIdx.x;
    const int tid  = threadIdx.x;
    const int lane = tid & 31;
    const int warp = tid >> 5;
    const uint32_t base_o = (uint32_t)o * (uint32_t)IN_;

#pragma unroll 1
    for (int g = 0; g < NGRP; ++g) {
        const int sbase = g * SGRP;

        uint64_t acc2[NPAIR];
#pragma unroll
        for (int jp = 0; jp < NPAIR; ++jp) acc2[jp] = 0ull;

#pragma unroll 1
        for (int ii = 0; ii < IN_ / TPB; ++ii) {
            const int i = ii * TPB + tid;
            const float mu = wmu[base_o + i];
            const float sg = wsig[base_o + i];
            const uint64_t mu2 = pk2(mu, mu);
            const uint64_t sg2 = pk2(sg, sg);
            const float* xp = x + (size_t)sbase * IN_ + i;

            // x1 init for s=sbase: sbase*2^22 + (base + i) + k1
            const uint32_t cb = addi((uint32_t)sbase,
                                     base_o + (uint32_t)i + wk.k1, c22);

#pragma unroll
            for (int jp = 0; jp < NPAIR; ++jp) {
                const uint32_t ca = cb + ((uint32_t)(2 * jp) << 22);
                const uint32_t bits_a = threefry_from_x1(wk, ca, one, rm);
                const uint32_t bits_b = threefry_from_x1(wk, ca + (1u << 22), one, rm);

                const float ua = u_of(bits_a);
                const float ub = u_of(bits_b);

                const uint64_t u2 = pk2(ua, ub);
                const uint64_t t2 = mul2(u2, u2);
                const uint64_t y2 = fma2(t2, pc.negone2, pc.one2);   // 1 - u^2 (exact)
                float ya, yb; upk2(ya, yb, y2);
                const float la = __log2f(ya);
                const float lb = __log2f(yb);
                const uint64_t l2  = pk2(la, lb);
                const uint64_t wc2 = fma2(l2, pc.negln2_2, pc.m2p5_2);

                uint64_t p2 = fma2(pc.c0, wc2, pc.c1);
                p2 = fma2(p2, wc2, pc.c2);
                p2 = fma2(p2, wc2, pc.c3);
                p2 = fma2(p2, wc2, pc.c4);
                p2 = fma2(p2, wc2, pc.c5);
                p2 = fma2(p2, wc2, pc.c6);
                p2 = fma2(p2, wc2, pc.c7);
                p2 = fma2(p2, wc2, pc.c8);

                uint64_t eps2 = mul2(p2, u2);

                if (__builtin_expect(fabsf(ua) >= UTH || fabsf(ub) >= UTH, 0)) {
                    float ea, eb; upk2(ea, eb, eps2);
                    if (fabsf(ua) >= UTH) ea = tail_eps(ua, la);
                    if (fabsf(ub) >= UTH) eb = tail_eps(ub, lb);
                    eps2 = pk2(ea, eb);
                }

                const uint64_t w2v = fma2(sg2, eps2, mu2);
                const float xa = xp[(2 * jp) * IN_];
                const float xb = xp[(2 * jp + 1) * IN_];
                acc2[jp] = fma2(w2v, pk2(xa, xb), acc2[jp]);
            }
        }

        // unpack + warp butterfly reduction; lane 0 stores the 8 partials
        float acc[SGRP];
#pragma unroll
        for (int jp = 0; jp < NPAIR; ++jp)
            upk2(acc[2 * jp], acc[2 * jp + 1], acc2[jp]);

#pragma unroll
        for (int j = 0; j < SGRP; ++j) {
#pragma unroll
            for (int m = 16; m >= 1; m >>= 1)
                acc[j] += __shfl_xor_sync(0xffffffffu, acc[j], m);
        }
        if (lane == 0) {
#pragma unroll
            for (int j = 0; j < SGRP; ++j)
                red[sbase + j][warp] = acc[j];
        }
    }

    __syncthreads();

    if (tid < S_) {
        float tot = 0.0f;
#pragma unroll
        for (int w = 0; w < TPB / 32; ++w) tot += red[tid][w];

        // bias epsilon: counter = s*OUT + o over bkey (sqrt2 folded)
        const uint32_t c1 = (uint32_t)(tid * OUT_ + o) + bk.k1;
        const float eb = bits_to_eps_scalar(threefry_from_x1(bk, c1, one, rm));
        out[tid * OUT_ + o] = tot + __fmaf_rn(bsig[o], eb, bmu[o]);
    }
}

// ---------------------------------------------------------------------------
static uint64_t hpk(float f) {
    uint32_t b; memcpy(&b, &f, 4);
    return ((uint64_t)b << 32) | (uint64_t)b;
}

extern "C" void kernel_launch(void* const* d_in, const int* in_sizes, int n_in,
                              void* d_out, int out_size)
{
    const float* x    = (const float*)d_in[0];
    const float* wmu  = (const float*)d_in[1];
    const float* wsig = (const float*)d_in[2];
    const float* bmu  = (const float*)d_in[3];
    const float* bsig = (const float*)d_in[4];
    float* out        = (float*)d_out;

    uint32_t wk0, wk1, bk0, bk1;
    h_threefry2x32(0u, 42u, 0u, 0u, wk0, wk1);
    h_threefry2x32(0u, 42u, 0u, 1u, bk0, bk1);

    TFKeys wk, bk;
    wk.k0 = wk0; wk.k1 = wk1; wk.k2 = wk0 ^ wk1 ^ 0x1BD11BDAu;
    wk.j1 = wk.k2 + 1u; wk.j2 = wk.k0 + 2u; wk.j3 = wk.k1 + 3u;
    wk.j4 = wk.k2 + 4u; wk.j5 = wk.k0 + 5u;

    bk.k0 = bk0; bk.k1 = bk1; bk.k2 = bk0 ^ bk1 ^ 0x1BD11BDAu;
    bk.j1 = bk.k2 + 1u; bk.j2 = bk.k0 + 2u; bk.j3 = bk.k1 + 3u;
    bk.j4 = bk.k2 + 4u; bk.j5 = bk.k0 + 5u;

    RotM rm;
    rm.m13 = 1u << 13; rm.m15 = 1u << 15; rm.m26 = 1u << 26; rm.m6  = 1u << 6;
    rm.m17 = 1u << 17; rm.m29 = 1u << 29; rm.m16 = 1u << 16; rm.m24 = 1u << 24;

    PC pc;
    pc.c0 = hpk(3.9740742e-08f);
    pc.c1 = hpk(4.8546264e-07f);
    pc.c2 = hpk(-4.9828285e-06f);
    pc.c3 = hpk(-6.2105203e-06f);
    pc.c4 = hpk(3.0911997e-04f);
    pc.c5 = hpk(-1.7730364e-03f);
    pc.c6 = hpk(-5.9081367e-03f);
    pc.c7 = hpk(3.4880266e-01f);
    pc.c8 = hpk(2.1233135e+00f);
    pc.one2     = hpk(1.0f);
    pc.negone2  = hpk(-1.0f);
    pc.negln2_2 = hpk(-0.69314718f);
    pc.m2p5_2   = hpk(-2.5f);

    bayes_linear_kernel<<<OUT_, TPB>>>(x, wmu, wsig, bmu, bsig, out,
                                       wk, bk, rm, pc, 1u, 1u << 22);
}

// round 7
// speedup vs baseline: 1.3537x; 1.3537x over previous
#include <cuda_runtime.h>
#include <cstdint>

#define S_   32
#define IN_  2048
#define OUT_ 2048
#define TPB  128                  // 4 warps/block -> 2048 blocks fit in ONE wave
#define NWARP (TPB / 32)
#define SGRP 8                    // samples per register group
#define NGRP (S_ / SGRP)

// ---------------------------------------------------------------------------
// Host-side threefry2x32 (subkey derivation for jax.random.key(42) only)
// ---------------------------------------------------------------------------
static inline uint32_t h_rotl32(uint32_t x, int r) {
    return (x << r) | (x >> (32 - r));
}
static inline void h_round(uint32_t& x0, uint32_t& x1, int r) {
    x0 += x1; x1 = h_rotl32(x1, r); x1 ^= x0;
}
static void h_threefry2x32(uint32_t k0, uint32_t k1, uint32_t c0, uint32_t c1,
                           uint32_t& o0, uint32_t& o1)
{
    const uint32_t k2 = k0 ^ k1 ^ 0x1BD11BDAu;
    uint32_t x0 = c0 + k0, x1 = c1 + k1;
    h_round(x0,x1,13); h_round(x0,x1,15); h_round(x0,x1,26); h_round(x0,x1,6);
    x0 += k1; x1 += k2 + 1u;
    h_round(x0,x1,17); h_round(x0,x1,29); h_round(x0,x1,16); h_round(x0,x1,24);
    x0 += k2; x1 += k0 + 2u;
    h_round(x0,x1,13); h_round(x0,x1,15); h_round(x0,x1,26); h_round(x0,x1,6);
    x0 += k0; x1 += k1 + 3u;
    h_round(x0,x1,17); h_round(x0,x1,29); h_round(x0,x1,16); h_round(x0,x1,24);
    x0 += k1; x1 += k2 + 4u;
    h_round(x0,x1,13); h_round(x0,x1,15); h_round(x0,x1,26); h_round(x0,x1,6);
    x0 += k2; x1 += k0 + 5u;
    o0 = x0; o1 = x1;
}

// ---------------------------------------------------------------------------
// Device threefry: adds as IMAD via opaque `one` (fma pipe); SHF/LOP3 on alu.
// (Round-4 proven-best form; mul.wide and f32x2 variants regressed.)
// ---------------------------------------------------------------------------
struct TFKeys {
    uint32_t k0, k1, k2;
    uint32_t j1, j2, j3, j4, j5;   // k2+1, k0+2, k1+3, k2+4, k0+5
};

__device__ __forceinline__ uint32_t addi(uint32_t a, uint32_t b, uint32_t one) {
    return a * one + b;            // IMAD -> fma pipe
}
__device__ __forceinline__ void tfr(uint32_t& x0, uint32_t& x1, int r, uint32_t one) {
    x0 = addi(x0, x1, one);
    x1 = __funnelshift_l(x1, x1, r);
    x1 ^= x0;
}
__device__ __forceinline__ uint32_t threefry_from_x1(const TFKeys k, uint32_t x1, uint32_t one) {
    uint32_t x0 = k.k0;            // c0 == 0

    tfr(x0,x1,13,one); tfr(x0,x1,15,one); tfr(x0,x1,26,one); tfr(x0,x1,6,one);
    x0 = addi(x0, k.k1, one); x1 = addi(x1, k.j1, one);
    tfr(x0,x1,17,one); tfr(x0,x1,29,one); tfr(x0,x1,16,one); tfr(x0,x1,24,one);
    x0 = addi(x0, k.k2, one); x1 = addi(x1, k.j2, one);
    tfr(x0,x1,13,one); tfr(x0,x1,15,one); tfr(x0,x1,26,one); tfr(x0,x1,6,one);
    x0 = addi(x0, k.k0, one); x1 = addi(x1, k.j3, one);
    tfr(x0,x1,17,one); tfr(x0,x1,29,one); tfr(x0,x1,16,one); tfr(x0,x1,24,one);
    x0 = addi(x0, k.k1, one); x1 = addi(x1, k.j4, one);
    tfr(x0,x1,13,one); tfr(x0,x1,15,one); tfr(x0,x1,26,one); tfr(x0,x1,6,one);
    x0 = addi(x0, k.k2, one); x1 = addi(x1, k.j5, one);

    return x0 ^ x1;
}

// ---------------------------------------------------------------------------
// bits -> eps = sqrt(2)*erfinv(u).  sqrt(2) folded into the coefficients.
//   u  = fma((float)(bits>>9), 2^-22, -0.99999994f)   (bit-exact vs JAX)
//   l  = log2(1-u^2)  [MUFU.LG2];  wc = fma(l, -ln2, -2.5) == w-2.5
// Central Giles poly always; rare tail (P=0.33%/lane) as divergent branch.
// ---------------------------------------------------------------------------
__device__ __forceinline__ float bits_to_eps(uint32_t bits) {
    float v = (float)(bits >> 9);
    float u = __fmaf_rn(v, 0x1p-22f, -0.99999994f);

    float t = __fmul_rn(u, u);
    float y = __fadd_rn(1.0f, -t);
    float l = __log2f(y);
    float wc = __fmaf_rn(l, -0.69314718f, -2.5f);   // w - 2.5

    float p;
    p = 3.9740742e-08f;
    p = __fmaf_rn(p, wc, 4.8546264e-07f);
    p = __fmaf_rn(p, wc, -4.9828285e-06f);
    p = __fmaf_rn(p, wc, -6.2105203e-06f);
    p = __fmaf_rn(p, wc, 3.0911997e-04f);
    p = __fmaf_rn(p, wc, -1.7730364e-03f);
    p = __fmaf_rn(p, wc, -5.9081367e-03f);
    p = __fmaf_rn(p, wc, 3.4880266e-01f);
    p = __fmaf_rn(p, wc, 2.1233135e+00f);

    if (wc >= 2.5f) {   // rare tail: |u| > 0.99666
        float w  = __fmul_rn(l, -0.69314718f);
        float ws = __fsqrt_rn(w) - 3.0f;
        p = -2.8314684e-04f;
        p = __fmaf_rn(p, ws, 1.4276590e-04f);
        p = __fmaf_rn(p, ws, 1.9082523e-03f);
        p = __fmaf_rn(p, ws, -5.1950109e-03f);
        p = __fmaf_rn(p, ws, 8.1168911e-03f);
        p = __fmaf_rn(p, ws, -1.0779785e-02f);
        p = __fmaf_rn(p, ws, 1.3348580e-02f);
        p = __fmaf_rn(p, ws, 1.4165810e+00f);
        p = __fmaf_rn(p, ws, 4.0064341e+00f);
    }
    return __fmul_rn(p, u);
}

// ---------------------------------------------------------------------------
// One block per output column o, 128 threads (4 warps). Outer loop: 4 groups
// of 8 samples (acc[8] in regs). Inner loop: i strided by 128 threads.
// Shuffle reduction at group end. counter = s*2^22 + (o*IN + i).
// Single wave: 2048 blocks * 4 warps, regs=32 -> all CTAs resident at once.
// ---------------------------------------------------------------------------
__global__ void __launch_bounds__(TPB)
bayes_linear_kernel(const float* __restrict__ x,
                    const float* __restrict__ wmu,
                    const float* __restrict__ wsig,
                    const float* __restrict__ bmu,
                    const float* __restrict__ bsig,
                    float* __restrict__ out,
                    TFKeys wk, TFKeys bk,
                    uint32_t one, uint32_t c22 /* == 1<<22, opaque */)
{
    __shared__ float red[S_][NWARP + 1];   // [sample][warp] partials

    const int o    = blockIdx.x;
    const int tid  = threadIdx.x;
    const int lane = tid & 31;
    const int warp = tid >> 5;
    const uint32_t base_o = (uint32_t)o * (uint32_t)IN_;

#pragma unroll 1
    for (int g = 0; g < NGRP; ++g) {
        const int sbase = g * SGRP;

        float acc[SGRP];
#pragma unroll
        for (int j = 0; j < SGRP; ++j) acc[j] = 0.0f;

#pragma unroll 1
        for (int ii = 0; ii < IN_ / TPB; ++ii) {
            const int i = ii * TPB + tid;
            const float mu = wmu[base_o + i];
            const float sg = wsig[base_o + i];
            const float* xp = x + (size_t)sbase * IN_ + i;

            // x1 init for j=0: sbase*2^22 + (base + i) + k1 ; per-j adds j*2^22
            const uint32_t cb = addi((uint32_t)sbase,
                                     base_o + (uint32_t)i + wk.k1, c22);

#pragma unroll
            for (int j = 0; j < SGRP; ++j) {
                const uint32_t bits = threefry_from_x1(wk, cb + ((uint32_t)j << 22), one);
                const float eps = bits_to_eps(bits);
                acc[j] = __fmaf_rn(__fmaf_rn(sg, eps, mu), xp[j * IN_], acc[j]);
            }
        }

        // warp butterfly reduction; lane 0 stores the 8 partials
#pragma unroll
        for (int j = 0; j < SGRP; ++j) {
#pragma unroll
            for (int m = 16; m >= 1; m >>= 1)
                acc[j] += __shfl_xor_sync(0xffffffffu, acc[j], m);
        }
        if (lane == 0) {
#pragma unroll
            for (int j = 0; j < SGRP; ++j)
                red[sbase + j][warp] = acc[j];
        }
    }

    __syncthreads();

    if (tid < S_) {
        float tot = 0.0f;
#pragma unroll
        for (int w = 0; w < NWARP; ++w) tot += red[tid][w];

        // bias epsilon: counter = s*OUT + o over bkey (sqrt2 already folded)
        const uint32_t c1 = (uint32_t)(tid * OUT_ + o);
        const float eb = bits_to_eps(threefry_from_x1(bk, c1 + bk.k1, one));
        out[tid * OUT_ + o] = tot + __fmaf_rn(bsig[o], eb, bmu[o]);
    }
}

// ---------------------------------------------------------------------------
extern "C" void kernel_launch(void* const* d_in, const int* in_sizes, int n_in,
                              void* d_out, int out_size)
{
    const float* x    = (const float*)d_in[0];
    const float* wmu  = (const float*)d_in[1];
    const float* wsig = (const float*)d_in[2];
    const float* bmu  = (const float*)d_in[3];
    const float* bsig = (const float*)d_in[4];
    float* out        = (float*)d_out;

    uint32_t wk0, wk1, bk0, bk1;
    h_threefry2x32(0u, 42u, 0u, 0u, wk0, wk1);
    h_threefry2x32(0u, 42u, 0u, 1u, bk0, bk1);

    TFKeys wk, bk;
    wk.k0 = wk0; wk.k1 = wk1; wk.k2 = wk0 ^ wk1 ^ 0x1BD11BDAu;
    wk.j1 = wk.k2 + 1u; wk.j2 = wk.k0 + 2u; wk.j3 = wk.k1 + 3u;
    wk.j4 = wk.k2 + 4u; wk.j5 = wk.k0 + 5u;

    bk.k0 = bk0; bk.k1 = bk1; bk.k2 = bk0 ^ bk1 ^ 0x1BD11BDAu;
    bk.j1 = bk.k2 + 1u; bk.j2 = bk.k0 + 2u; bk.j3 = bk.k1 + 3u;
    bk.j4 = bk.k2 + 4u; bk.j5 = bk.k0 + 5u;

    bayes_linear_kernel<<<OUT_, TPB>>>(x, wmu, wsig, bmu, bsig, out,
                                       wk, bk, 1u, 1u << 22);
}

// round 8
// speedup vs baseline: 1.4674x; 1.0841x over previous
#include <cuda_runtime.h>
#include <cstdint>

#define S_    32
#define IN_   2048
#define OUT_  2048
#define TPB   256
#define SGRP  8                   // samples per block
#define QBLK  (S_ / SGRP)         // 4 s-quarters -> grid = OUT_ * QBLK

// ---------------------------------------------------------------------------
// Host-side threefry2x32 (subkey derivation for jax.random.key(42) only)
// ---------------------------------------------------------------------------
static inline uint32_t h_rotl32(uint32_t x, int r) {
    return (x << r) | (x >> (32 - r));
}
static inline void h_round(uint32_t& x0, uint32_t& x1, int r) {
    x0 += x1; x1 = h_rotl32(x1, r); x1 ^= x0;
}
static void h_threefry2x32(uint32_t k0, uint32_t k1, uint32_t c0, uint32_t c1,
                           uint32_t& o0, uint32_t& o1)
{
    const uint32_t k2 = k0 ^ k1 ^ 0x1BD11BDAu;
    uint32_t x0 = c0 + k0, x1 = c1 + k1;
    h_round(x0,x1,13); h_round(x0,x1,15); h_round(x0,x1,26); h_round(x0,x1,6);
    x0 += k1; x1 += k2 + 1u;
    h_round(x0,x1,17); h_round(x0,x1,29); h_round(x0,x1,16); h_round(x0,x1,24);
    x0 += k2; x1 += k0 + 2u;
    h_round(x0,x1,13); h_round(x0,x1,15); h_round(x0,x1,26); h_round(x0,x1,6);
    x0 += k0; x1 += k1 + 3u;
    h_round(x0,x1,17); h_round(x0,x1,29); h_round(x0,x1,16); h_round(x0,x1,24);
    x0 += k1; x1 += k2 + 4u;
    h_round(x0,x1,13); h_round(x0,x1,15); h_round(x0,x1,26); h_round(x0,x1,6);
    x0 += k2; x1 += k0 + 5u;
    o0 = x0; o1 = x1;
}

// ---------------------------------------------------------------------------
// Device threefry: adds as IMAD via opaque `one` (fma pipe); SHF/LOP3 on alu.
// (Round-4 proven-best form.)
// ---------------------------------------------------------------------------
struct TFKeys {
    uint32_t k0, k1, k2;
    uint32_t j1, j2, j3, j4, j5;   // k2+1, k0+2, k1+3, k2+4, k0+5
};

__device__ __forceinline__ uint32_t addi(uint32_t a, uint32_t b, uint32_t one) {
    return a * one + b;            // IMAD -> fma pipe
}
__device__ __forceinline__ void tfr(uint32_t& x0, uint32_t& x1, int r, uint32_t one) {
    x0 = addi(x0, x1, one);
    x1 = __funnelshift_l(x1, x1, r);
    x1 ^= x0;
}
__device__ __forceinline__ uint32_t threefry_from_x1(const TFKeys k, uint32_t x1, uint32_t one) {
    uint32_t x0 = k.k0;            // c0 == 0

    tfr(x0,x1,13,one); tfr(x0,x1,15,one); tfr(x0,x1,26,one); tfr(x0,x1,6,one);
    x0 = addi(x0, k.k1, one); x1 = addi(x1, k.j1, one);
    tfr(x0,x1,17,one); tfr(x0,x1,29,one); tfr(x0,x1,16,one); tfr(x0,x1,24,one);
    x0 = addi(x0, k.k2, one); x1 = addi(x1, k.j2, one);
    tfr(x0,x1,13,one); tfr(x0,x1,15,one); tfr(x0,x1,26,one); tfr(x0,x1,6,one);
    x0 = addi(x0, k.k0, one); x1 = addi(x1, k.j3, one);
    tfr(x0,x1,17,one); tfr(x0,x1,29,one); tfr(x0,x1,16,one); tfr(x0,x1,24,one);
    x0 = addi(x0, k.k1, one); x1 = addi(x1, k.j4, one);
    tfr(x0,x1,13,one); tfr(x0,x1,15,one); tfr(x0,x1,26,one); tfr(x0,x1,6,one);
    x0 = addi(x0, k.k2, one); x1 = addi(x1, k.j5, one);

    return x0 ^ x1;
}

// ---------------------------------------------------------------------------
// bits -> eps = sqrt(2)*erfinv(u), sqrt(2) folded into coefficients.
// Central poly truncated to 7 coefficients (dropped terms contribute
// <= 2.5e-4 abs at |wc|=2.5 edge, ~1e-5 rms — 100x inside the 1e-3 budget).
// Rare tail (P=0.33%/lane) as divergent branch.
// ---------------------------------------------------------------------------
__device__ __forceinline__ float bits_to_eps(uint32_t bits) {
    float v = (float)(bits >> 9);
    float u = __fmaf_rn(v, 0x1p-22f, -0.99999994f);

    float t = __fmul_rn(u, u);
    float y = __fadd_rn(1.0f, -t);
    float l = __log2f(y);
    float wc = __fmaf_rn(l, -0.69314718f, -2.5f);   // w - 2.5

    float p;
    p = -4.9828285e-06f;
    p = __fmaf_rn(p, wc, -6.2105203e-06f);
    p = __fmaf_rn(p, wc, 3.0911997e-04f);
    p = __fmaf_rn(p, wc, -1.7730364e-03f);
    p = __fmaf_rn(p, wc, -5.9081367e-03f);
    p = __fmaf_rn(p, wc, 3.4880266e-01f);
    p = __fmaf_rn(p, wc, 2.1233135e+00f);

    if (wc >= 2.5f) {   // rare tail: |u| > 0.99666
        float w  = __fmul_rn(l, -0.69314718f);
        float ws = __fsqrt_rn(w) - 3.0f;
        p = -2.8314684e-04f;
        p = __fmaf_rn(p, ws, 1.4276590e-04f);
        p = __fmaf_rn(p, ws, 1.9082523e-03f);
        p = __fmaf_rn(p, ws, -5.1950109e-03f);
        p = __fmaf_rn(p, ws, 8.1168911e-03f);
        p = __fmaf_rn(p, ws, -1.0779785e-02f);
        p = __fmaf_rn(p, ws, 1.3348580e-02f);
        p = __fmaf_rn(p, ws, 1.4165810e+00f);
        p = __fmaf_rn(p, ws, 4.0064341e+00f);
    }
    return __fmul_rn(p, u);
}

// ---------------------------------------------------------------------------
// grid = OUT_*4: block = (output column o, s-quarter q). 8 samples per block
// in registers; 256 threads stride IN. Fine-grained blocks (~4x shorter than
// R4) smooth the end-of-kernel drain that capped occupancy at 77.5%.
// counter = s*2^22 + (o*IN + i), s = q*8 + j.
// ---------------------------------------------------------------------------
__global__ void __launch_bounds__(TPB)
bayes_linear_kernel(const float* __restrict__ x,
                    const float* __restrict__ wmu,
                    const float* __restrict__ wsig,
                    const float* __restrict__ bmu,
                    const float* __restrict__ bsig,
                    float* __restrict__ out,
                    TFKeys wk, TFKeys bk,
                    uint32_t one, uint32_t c22 /* == 1<<22, opaque */)
{
    __shared__ float red[SGRP][(TPB / 32) + 1];   // [sample][warp] partials

    const int bid  = blockIdx.x;
    const int o    = bid & (OUT_ - 1);
    const int q    = bid >> 11;                   // s-quarter, 2048 == 1<<11
    const int sbase = q * SGRP;
    const int tid  = threadIdx.x;
    const int lane = tid & 31;
    const int warp = tid >> 5;
    const uint32_t base_o = (uint32_t)o * (uint32_t)IN_;

    float acc[SGRP];
#pragma unroll
    for (int j = 0; j < SGRP; ++j) acc[j] = 0.0f;

#pragma unroll 1
    for (int ii = 0; ii < IN_ / TPB; ++ii) {
        const int i = ii * TPB + tid;
        const float mu = wmu[base_o + i];
        const float sg = wsig[base_o + i];
        const float* xp = x + (size_t)sbase * IN_ + i;

        // x1 init for j=0: sbase*2^22 + (base + i) + k1 ; per-j adds j*2^22
        const uint32_t cb = addi((uint32_t)sbase,
                                 base_o + (uint32_t)i + wk.k1, c22);

#pragma unroll
        for (int j = 0; j < SGRP; ++j) {
            const uint32_t bits = threefry_from_x1(wk, cb + ((uint32_t)j << 22), one);
            const float eps = bits_to_eps(bits);
            acc[j] = __fmaf_rn(__fmaf_rn(sg, eps, mu), xp[j * IN_], acc[j]);
        }
    }

    // warp butterfly reduction; lane 0 stores the 8 partials
#pragma unroll
    for (int j = 0; j < SGRP; ++j) {
#pragma unroll
        for (int m = 16; m >= 1; m >>= 1)
            acc[j] += __shfl_xor_sync(0xffffffffu, acc[j], m);
    }
    if (lane == 0) {
#pragma unroll
        for (int j = 0; j < SGRP; ++j)
            red[j][warp] = acc[j];
    }

    __syncthreads();

    if (tid < SGRP) {
        float tot = 0.0f;
#pragma unroll
        for (int w = 0; w < TPB / 32; ++w) tot += red[tid][w];

        const int s = sbase + tid;
        // bias epsilon: counter = s*OUT + o over bkey (sqrt2 already folded)
        const uint32_t c1 = (uint32_t)(s * OUT_ + o);
        const float eb = bits_to_eps(threefry_from_x1(bk, c1 + bk.k1, one));
        out[s * OUT_ + o] = tot + __fmaf_rn(bsig[o], eb, bmu[o]);
    }
}

// ---------------------------------------------------------------------------
extern "C" void kernel_launch(void* const* d_in, const int* in_sizes, int n_in,
                              void* d_out, int out_size)
{
    const float* x    = (const float*)d_in[0];
    const float* wmu  = (const float*)d_in[1];
    const float* wsig = (const float*)d_in[2];
    const float* bmu  = (const float*)d_in[3];
    const float* bsig = (const float*)d_in[4];
    float* out        = (float*)d_out;

    uint32_t wk0, wk1, bk0, bk1;
    h_threefry2x32(0u, 42u, 0u, 0u, wk0, wk1);
    h_threefry2x32(0u, 42u, 0u, 1u, bk0, bk1);

    TFKeys wk, bk;
    wk.k0 = wk0; wk.k1 = wk1; wk.k2 = wk0 ^ wk1 ^ 0x1BD11BDAu;
    wk.j1 = wk.k2 + 1u; wk.j2 = wk.k0 + 2u; wk.j3 = wk.k1 + 3u;
    wk.j4 = wk.k2 + 4u; wk.j5 = wk.k0 + 5u;

    bk.k0 = bk0; bk.k1 = bk1; bk.k2 = bk0 ^ bk1 ^ 0x1BD11BDAu;
    bk.j1 = bk.k2 + 1u; bk.j2 = bk.k0 + 2u; bk.j3 = bk.k1 + 3u;
    bk.j4 = bk.k2 + 4u; bk.j5 = bk.k0 + 5u;

    bayes_linear_kernel<<<OUT_ * QBLK, TPB>>>(x, wmu, wsig, bmu, bsig, out,
                                              wk, bk, 1u, 1u << 22);
}